// round 16
// baseline (speedup 1.0000x reference)
#include <cuda_runtime.h>
#include <cuda_fp16.h>
#include <cstdint>
#include <math.h>

#define NTOK  65536
#define DIN   512
#define DK    256
#define MS    64

// ---------------- static scratch (fp16) ----------------
__device__ __half g_encw_h[DK * DIN];
__device__ __half g_mem_h[MS * DK];
__device__ __half g_dt_h[MS * DIN];

// ======================= helpers =======================
__device__ __forceinline__ uint32_t smem_u32(const void* p) {
    uint32_t a;
    asm("{ .reg .u64 t; cvta.to.shared.u64 t, %1; cvt.u32.u64 %0, t; }"
        : "=r"(a) : "l"(p));
    return a;
}
__device__ __forceinline__ uint32_t pack_h2(float a, float b) {
    __half2 t = __floats2half2_rn(a, b);
    return *reinterpret_cast<uint32_t*>(&t);
}
__device__ __forceinline__ void split2h(float a, float b, uint32_t& hi, uint32_t& lo) {
    __half ha = __float2half_rn(a), hb = __float2half_rn(b);
    __half2 hp; hp.x = ha; hp.y = hb;
    hi = *reinterpret_cast<uint32_t*>(&hp);
    lo = pack_h2(a - __half2float(ha), b - __half2float(hb));
}
__device__ __forceinline__ void sts64(uint32_t addr, unsigned long long v) {
    asm volatile("st.shared.b64 [%0], %1;" :: "r"(addr), "l"(v) : "memory");
}
__device__ __forceinline__ void sts32(uint32_t addr, uint32_t v) {
    asm volatile("st.shared.b32 [%0], %1;" :: "r"(addr), "r"(v) : "memory");
}
__device__ __forceinline__ void cp16(uint32_t saddr, const void* g) {
    asm volatile("cp.async.cg.shared.global [%0], [%1], 16;"
                 :: "r"(saddr), "l"(g) : "memory");
}
#define CP_COMMIT() asm volatile("cp.async.commit_group;" ::: "memory")
#define CP_WAIT(n)  asm volatile("cp.async.wait_group %0;" :: "n"(n) : "memory")

__device__ __forceinline__ void ldsm_x4(uint32_t* r, uint32_t addr) {
    asm volatile("ldmatrix.sync.aligned.m8n8.x4.shared.b16 {%0,%1,%2,%3}, [%4];"
                 : "=r"(r[0]), "=r"(r[1]), "=r"(r[2]), "=r"(r[3]) : "r"(addr));
}
__device__ __forceinline__ void ldsm_x4_t(uint32_t* r, uint32_t addr) {
    asm volatile("ldmatrix.sync.aligned.m8n8.x4.trans.shared.b16 {%0,%1,%2,%3}, [%4];"
                 : "=r"(r[0]), "=r"(r[1]), "=r"(r[2]), "=r"(r[3]) : "r"(addr));
}
__device__ __forceinline__ void mma16816(float* d, const uint32_t* a,
                                         uint32_t b0, uint32_t b1) {
    asm volatile(
        "mma.sync.aligned.m16n8k16.row.col.f32.f16.f16.f32 "
        "{%0,%1,%2,%3}, {%4,%5,%6,%7}, {%8,%9}, {%0,%1,%2,%3};"
        : "+f"(d[0]), "+f"(d[1]), "+f"(d[2]), "+f"(d[3])
        : "r"(a[0]), "r"(a[1]), "r"(a[2]), "r"(a[3]), "r"(b0), "r"(b1));
}
__device__ __forceinline__ void stcs2(float* p, float2 v) {
    asm volatile("st.global.cs.v2.f32 [%0], {%1,%2};" :: "l"(p), "f"(v.x), "f"(v.y)
                 : "memory");
}

// ---------------- prep 1: enc_w, mem -> fp16 ----------------
__global__ void prep_cvt(const float* __restrict__ ew, const float* __restrict__ mm)
{
    int i = blockIdx.x * blockDim.x + threadIdx.x;
    {
        float2 v = __ldg((const float2*)ew + i);
        *((uint32_t*)g_encw_h + i) = pack_h2(v.x, v.y);
    }
    if (i < MS * DK / 2) {
        float2 v = __ldg((const float2*)mm + i);
        *((uint32_t*)g_mem_h + i) = pack_h2(v.x, v.y);
    }
}

// ---------------- prep 2: Dt[s][n] = dec_w[n,:].mem[s,:] -> fp16 ----------------
__global__ void prep_dt(const float* __restrict__ dw, const float* __restrict__ mm)
{
    int s = threadIdx.x & 63;
    int n = blockIdx.x * 4 + (threadIdx.x >> 6);
    const float4* wr = (const float4*)(dw + (size_t)n * DK);
    const float4* mr = (const float4*)(mm + (size_t)s * DK);
    float acc = 0.0f;
#pragma unroll 8
    for (int k = 0; k < DK / 4; k++) {
        float4 a = __ldg(wr + k), b = __ldg(mr + k);
        acc += a.x * b.x + a.y * b.y + a.z * b.z + a.w * b.w;
    }
    g_dt_h[s * DIN + n] = __float2half_rn(acc);
}

// ===========================================================================
// Fused kernel: 128 tokens/block, 256 threads (8 warps), grid 512.
//  Phase E: encode BM=128, BN=128 x2 halves, BK=32, warp tile 32x64,
//           single fp16, 1-pass MMA. E = tanh(..) -> SMEM only.
//  Phase A: logits -> softmax -> att -> memo -> recon (same 8 warps).
// SMEM: [E 67584][chunk 40960] ; mem overlays chunk, Dt overlays E.
// ===========================================================================
#define EROW   528
#define ESZ    (128 * EROW)                // 67584
#define RSB    80
#define APART  (128 * RSB)                 // 10240
#define BUFSZ  (2 * APART)                 // 20480 (A | W)
#define CHREG  (2 * BUFSZ)                 // 40960
#define DTROW  1040
#define FU_SMEM (ESZ + CHREG)              // 108544

__global__ void __launch_bounds__(256, 2)
fused_all(const float* __restrict__ seq, const float* __restrict__ enc_b,
          float* __restrict__ att_out, float* __restrict__ mem_out,
          float* __restrict__ recon, const float* __restrict__ dec_b)
{
    extern __shared__ char smc[];
    const uint32_t sb = smem_u32(smc);
    const uint32_t sE  = sb;
    const uint32_t sCH = sb + ESZ;
    const uint32_t sM  = sCH;              // mem bank after encode
    const uint32_t sD  = sb;               // Dt after logits (over E)

    const int tid = threadIdx.x, wid = tid >> 5, lane = tid & 31;
    const int wm = wid & 3, wn = wid >> 2;
    const size_t t0 = (size_t)blockIdx.x * 128;

    const int lr = lane & 15, half = lane >> 4;
    const int tq = lane >> 2, tr = lane & 3;

    // ================= Phase E: encode =================
    float4 av[4];
    auto issue_w = [&](int h, int c, int buf) {
        const uint32_t base = sCH + buf * BUFSZ + APART;
#pragma unroll
        for (int l = 0; l < 2; l++) {
            int idx = tid + l * 256;
            int row = idx >> 2, seg = idx & 3;
            cp16(base + row * RSB + seg * 16,
                 g_encw_h + (size_t)(h * 128 + row) * DIN + c * 32 + seg * 8);
        }
    };
    auto load_a = [&](int c) {
#pragma unroll
        for (int l = 0; l < 4; l++) {
            int idx = tid + l * 256;
            int row = idx >> 3, q = idx & 7;
            av[l] = __ldg((const float4*)(seq + (t0 + row) * DIN + c * 32 + q * 4));
        }
    };
    auto store_a = [&](int buf) {
        const uint32_t base = sCH + buf * BUFSZ;
#pragma unroll
        for (int l = 0; l < 4; l++) {
            int idx = tid + l * 256;
            int row = idx >> 3, q = idx & 7;
            unsigned long long hv =
                (unsigned long long)pack_h2(av[l].x, av[l].y) |
                ((unsigned long long)pack_h2(av[l].z, av[l].w) << 32);
            sts64(base + row * RSB + q * 8, hv);
        }
    };

    for (int h = 0; h < 2; h++) {
        float acc[2][8][4];
#pragma unroll
        for (int i = 0; i < 2; i++)
#pragma unroll
            for (int j = 0; j < 8; j++)
#pragma unroll
                for (int k = 0; k < 4; k++) acc[i][j][k] = 0.0f;

        issue_w(h, 0, 0); CP_COMMIT();
        load_a(0); store_a(0);

        for (int c = 0; c < 16; c++) {
            CP_WAIT(0);
            __syncthreads();
            if (c + 1 < 16) {
                issue_w(h, c + 1, (c + 1) & 1); CP_COMMIT();
                load_a(c + 1);
            }
            {
                const uint32_t base = sCH + (c & 1) * BUFSZ;
                const uint32_t lh = half * 16;
#pragma unroll
                for (int ks = 0; ks < 2; ks++) {
                    uint32_t ahf[2][4], whf[4][4];
#pragma unroll
                    for (int mt = 0; mt < 2; mt++) {
                        uint32_t ao = (wm * 32 + mt * 16 + lr) * RSB + ks * 32 + lh;
                        ldsm_x4(ahf[mt], base + ao);
                    }
#pragma unroll
                    for (int g = 0; g < 4; g++) {
                        uint32_t wo = (wn * 64 + g * 16 + lr) * RSB + ks * 32 + lh;
                        ldsm_x4(whf[g], base + APART + wo);
                    }
#pragma unroll
                    for (int mt = 0; mt < 2; mt++)
#pragma unroll
                        for (int g = 0; g < 4; g++) {
                            mma16816(acc[mt][2 * g],     ahf[mt], whf[g][0], whf[g][2]);
                            mma16816(acc[mt][2 * g + 1], ahf[mt], whf[g][1], whf[g][3]);
                        }
                }
            }
            if (c + 1 < 16) store_a((c + 1) & 1);
        }

        // epilogue: tanh + bias -> E smem (single fp16)
#pragma unroll
        for (int mt = 0; mt < 2; mt++) {
            int row = wm * 32 + mt * 16 + tq;
#pragma unroll
            for (int nt = 0; nt < 8; nt++) {
                int col = h * 128 + wn * 64 + nt * 8 + tr * 2;
                float bx = __ldg(enc_b + col), by = __ldg(enc_b + col + 1);
                float v0 = tanhf(acc[mt][nt][0] + bx), v1 = tanhf(acc[mt][nt][1] + by);
                float v2 = tanhf(acc[mt][nt][2] + bx), v3 = tanhf(acc[mt][nt][3] + by);
                sts32(sE + row * EROW + col * 2, pack_h2(v0, v1));
                sts32(sE + (row + 8) * EROW + col * 2, pack_h2(v2, v3));
            }
        }
    }

    __syncthreads();    // chunk region fully retired; E writes in flight

    // load mem bank into chunk region
#pragma unroll
    for (int it = 0; it < 8; it++) {
        int idx = tid + it * 256;
        int row = idx >> 5, c = idx & 31;
        cp16(sM + row * EROW + c * 16, g_mem_h + row * DK + c * 8);
    }
    CP_COMMIT();
    CP_WAIT(0);
    __syncthreads();    // E + mem visible to all warps

    // ================= Phase A =================
    const int r0 = wid * 16;
    float S[8][4];
#pragma unroll
    for (int i = 0; i < 8; i++)
#pragma unroll
        for (int j = 0; j < 4; j++) S[i][j] = 0.0f;

#pragma unroll
    for (int ks = 0; ks < 16; ks++) {
        uint32_t aoff = (r0 + lr) * EROW + ks * 32 + half * 16;
        uint32_t ahf[4], bh[4][4];
        ldsm_x4(ahf, sE + aoff);
        const int kbyte = ks * 32 + half * 16;
#pragma unroll
        for (int g = 0; g < 4; g++)
            ldsm_x4(bh[g], sM + (g * 16 + lr) * EROW + kbyte);
#pragma unroll
        for (int g = 0; g < 4; g++) {
            mma16816(S[2 * g],     ahf, bh[g][0], bh[g][2]);
            mma16816(S[2 * g + 1], ahf, bh[g][1], bh[g][3]);
        }
    }

    __syncthreads();    // E dead

    // prefetch Dt over E region
#pragma unroll
    for (int it = 0; it < 16; it++) {
        int idx = tid + it * 256;
        int row = idx >> 6, c = idx & 63;
        cp16(sD + row * DTROW + c * 16, g_dt_h + row * DIN + c * 8);
    }
    CP_COMMIT();

    // softmax (register-only)
    float m0 = -1e30f, m1 = -1e30f;
#pragma unroll
    for (int nt = 0; nt < 8; nt++) {
        m0 = fmaxf(m0, fmaxf(S[nt][0], S[nt][1]));
        m1 = fmaxf(m1, fmaxf(S[nt][2], S[nt][3]));
    }
    m0 = fmaxf(m0, __shfl_xor_sync(0xffffffffu, m0, 1));
    m0 = fmaxf(m0, __shfl_xor_sync(0xffffffffu, m0, 2));
    m1 = fmaxf(m1, __shfl_xor_sync(0xffffffffu, m1, 1));
    m1 = fmaxf(m1, __shfl_xor_sync(0xffffffffu, m1, 2));
    float s0 = 0.0f, s1 = 0.0f;
#pragma unroll
    for (int nt = 0; nt < 8; nt++) {
        S[nt][0] = expf((S[nt][0] - m0) * 0.0625f); s0 += S[nt][0];
        S[nt][1] = expf((S[nt][1] - m0) * 0.0625f); s0 += S[nt][1];
        S[nt][2] = expf((S[nt][2] - m1) * 0.0625f); s1 += S[nt][2];
        S[nt][3] = expf((S[nt][3] - m1) * 0.0625f); s1 += S[nt][3];
    }
    s0 += __shfl_xor_sync(0xffffffffu, s0, 1);
    s0 += __shfl_xor_sync(0xffffffffu, s0, 2);
    s1 += __shfl_xor_sync(0xffffffffu, s1, 1);
    s1 += __shfl_xor_sync(0xffffffffu, s1, 2);
    float i0 = 1.0f / s0, i1 = 1.0f / s1;
#pragma unroll
    for (int nt = 0; nt < 8; nt++) {
        S[nt][0] *= i0; S[nt][1] *= i0; S[nt][2] *= i1; S[nt][3] *= i1;
    }

    uint32_t Ph[4][4], Pl[4][4];
#pragma unroll
    for (int kt = 0; kt < 4; kt++) {
        split2h(S[2 * kt][0],     S[2 * kt][1],     Ph[kt][0], Pl[kt][0]);
        split2h(S[2 * kt][2],     S[2 * kt][3],     Ph[kt][1], Pl[kt][1]);
        split2h(S[2 * kt + 1][0], S[2 * kt + 1][1], Ph[kt][2], Pl[kt][2]);
        split2h(S[2 * kt + 1][2], S[2 * kt + 1][3], Ph[kt][3], Pl[kt][3]);
    }

    const size_t ra = t0 + r0 + tq;
#pragma unroll
    for (int nt = 0; nt < 8; nt++) {
        float2 o0, o1;
        o0.x = S[nt][0]; o0.y = S[nt][1];
        o1.x = S[nt][2]; o1.y = S[nt][3];
        stcs2(att_out + ra * MS + nt * 8 + tr * 2, o0);
        stcs2(att_out + (ra + 8) * MS + nt * 8 + tr * 2, o1);
    }

    // memo = P @ mem (2-pass)
    const int lr8 = lane & 7, kh = (lane >> 3) & 1, nh = lane >> 4;
#pragma unroll
    for (int nc = 0; nc < 4; nc++) {
        float acc2[8][4];
#pragma unroll
        for (int i = 0; i < 8; i++)
#pragma unroll
            for (int j = 0; j < 4; j++) acc2[i][j] = 0.0f;
#pragma unroll
        for (int kt = 0; kt < 4; kt++) {
            uint32_t bh[4][4];
#pragma unroll
            for (int g2 = 0; g2 < 4; g2++) {
                uint32_t boff = (uint32_t)(kt * 16 + kh * 8 + lr8) * EROW +
                                (nc * 64 + g2 * 16 + nh * 8) * 2;
                ldsm_x4_t(bh[g2], sM + boff);
            }
#pragma unroll
            for (int g2 = 0; g2 < 4; g2++) {
                mma16816(acc2[2 * g2],     Ph[kt], bh[g2][0], bh[g2][1]);
                mma16816(acc2[2 * g2 + 1], Ph[kt], bh[g2][2], bh[g2][3]);
            }
#pragma unroll
            for (int g2 = 0; g2 < 4; g2++) {
                mma16816(acc2[2 * g2],     Pl[kt], bh[g2][0], bh[g2][1]);
                mma16816(acc2[2 * g2 + 1], Pl[kt], bh[g2][2], bh[g2][3]);
            }
        }
#pragma unroll
        for (int nt2 = 0; nt2 < 8; nt2++) {
            int gc = nc * 64 + nt2 * 8 + tr * 2;
            float2 o0, o1;
            o0.x = acc2[nt2][0]; o0.y = acc2[nt2][1];
            o1.x = acc2[nt2][2]; o1.y = acc2[nt2][3];
            stcs2(mem_out + ra * DK + gc, o0);
            stcs2(mem_out + (ra + 8) * DK + gc, o1);
        }
    }

    CP_WAIT(0);
    __syncthreads();    // Dt visible

    // recon = P @ Dt + dec_b (2-pass)
#pragma unroll
    for (int nc = 0; nc < 8; nc++) {
        float acc2[8][4];
#pragma unroll
        for (int i = 0; i < 8; i++)
#pragma unroll
            for (int j = 0; j < 4; j++) acc2[i][j] = 0.0f;
#pragma unroll
        for (int kt = 0; kt < 4; kt++) {
            uint32_t bh[4][4];
#pragma unroll
            for (int g2 = 0; g2 < 4; g2++) {
                uint32_t boff = (uint32_t)(kt * 16 + kh * 8 + lr8) * DTROW +
                                (nc * 64 + g2 * 16 + nh * 8) * 2;
                ldsm_x4_t(bh[g2], sD + boff);
            }
#pragma unroll
            for (int g2 = 0; g2 < 4; g2++) {
                mma16816(acc2[2 * g2],     Ph[kt], bh[g2][0], bh[g2][1]);
                mma16816(acc2[2 * g2 + 1], Ph[kt], bh[g2][2], bh[g2][3]);
            }
#pragma unroll
            for (int g2 = 0; g2 < 4; g2++) {
                mma16816(acc2[2 * g2],     Pl[kt], bh[g2][0], bh[g2][1]);
                mma16816(acc2[2 * g2 + 1], Pl[kt], bh[g2][2], bh[g2][3]);
            }
        }
#pragma unroll
        for (int nt2 = 0; nt2 < 8; nt2++) {
            int gc = nc * 64 + nt2 * 8 + tr * 2;
            float2 b2 = *(const float2*)(dec_b + gc);
            float2 o0, o1;
            o0.x = acc2[nt2][0] + b2.x; o0.y = acc2[nt2][1] + b2.y;
            o1.x = acc2[nt2][2] + b2.x; o1.y = acc2[nt2][3] + b2.y;
            stcs2(recon + ra * DIN + gc, o0);
            stcs2(recon + (ra + 8) * DIN + gc, o1);
        }
    }
}

// ---------------------------------------------------------------------------
extern "C" void kernel_launch(void* const* d_in, const int* in_sizes, int n_in,
                              void* d_out, int out_size)
{
    const float* seq   = (const float*)d_in[0];
    const float* enc_w = (const float*)d_in[1];
    const float* enc_b = (const float*)d_in[2];
    const float* mem   = (const float*)d_in[3];
    const float* dec_w = (const float*)d_in[4];
    const float* dec_b = (const float*)d_in[5];

    float* recon = (float*)d_out;
    float* att   = recon + (size_t)NTOK * DIN;
    float* memo  = att   + (size_t)NTOK * MS;

    cudaFuncSetAttribute(fused_all,
                         cudaFuncAttributeMaxDynamicSharedMemorySize, FU_SMEM);

    prep_cvt<<<DK * DIN / 2 / 256, 256>>>(enc_w, mem);
    prep_dt<<<DIN / 4, 256>>>(dec_w, mem);

    fused_all<<<NTOK / 128, 256, FU_SMEM>>>(seq, enc_b, att, memo, recon, dec_b);
}